// round 6
// baseline (speedup 1.0000x reference)
#include <cuda_runtime.h>
#include <cuda_fp16.h>
#include <cuda_bf16.h>

// ---------------------------------------------------------------------------
// GNN: 4x GCNConv (3->16->32->48->64, relu) + global max pool + 2-layer MLP
// Round-5 (resubmit after infra failure): fully predicated gathers (dummy
// zero-row at index n -> MLP=U for every node, no serial remainder),
// atomic-free fill via edge ranks.
// ---------------------------------------------------------------------------

#define N_MAX 131072
#define E_MAX 3400000
#define G_MAX 512

__device__ int    g_deg[N_MAX];
__device__ int    g_off[N_MAX + 1];
__device__ int    g_rank[E_MAX];
__device__ int    g_src[E_MAX];
__device__ int    g_bsum[256];
__device__ int    g_boff[256];
__device__ float  g_dinv[N_MAX];
__device__ uint2  g_s0[N_MAX + 1];        // layer-1 input as half4, dinv-scaled (+dummy)
__device__ uint2  g_hA[(N_MAX + 1) * 16]; // half feature buffer (<=64 ch, padded)
__device__ uint2  g_hB[(N_MAX + 1) * 16]; // half feature buffer
__device__ float  g_pool[G_MAX * 64];

// ---------------------------- CSR construction ----------------------------

__global__ void init_kernel(int n, int gtot) {
    int i = blockIdx.x * blockDim.x + threadIdx.x;
    int tot = (n > gtot) ? n : gtot;
    for (; i < tot; i += gridDim.x * blockDim.x) {
        if (i < n) g_deg[i] = 0;
        if (i < gtot) g_pool[i] = 0.0f;   // relu outputs >= 0 -> 0 is max-identity
    }
    // zero the dummy rows (index n) used by predicated gathers
    int t = blockIdx.x * blockDim.x + threadIdx.x;
    if (t < 16) {
        uint2 z; z.x = 0u; z.y = 0u;
        if (t == 0) g_s0[n] = z;
        if (t < 4)  g_hA[n * 4 + t]  = z;   // as CIN=16 input
        g_hA[n * 16 + t] = z;               // as CIN=48 input
        if (t < 8)  g_hB[n * 8 + t]  = z;   // as CIN=32 input
    }
}

// histogram + per-edge rank (rank = position among same-col edges)
__global__ void hist_rank_kernel(const int* __restrict__ col, int e) {
    int i = blockIdx.x * blockDim.x + threadIdx.x;
    int e2 = e >> 1;
    if (i < e2) {
        int2 c = reinterpret_cast<const int2*>(col)[i];
        int r0 = atomicAdd(&g_deg[c.x], 1);
        int r1 = atomicAdd(&g_deg[c.y], 1);
        reinterpret_cast<int2*>(g_rank)[i] = make_int2(r0, r1);
    }
    if (i == 0 && (e & 1))
        g_rank[e - 1] = atomicAdd(&g_deg[col[e - 1]], 1);
}

// two-level exclusive scan of g_deg -> g_off
__global__ void scan_local(int n) {
    __shared__ int sm[256];
    int b = blockIdx.x, t = threadIdx.x;
    int i0 = b * 512 + 2 * t, i1 = i0 + 1;
    int v0 = (i0 < n) ? g_deg[i0] : 0;
    int v1 = (i1 < n) ? g_deg[i1] : 0;
    sm[t] = v0 + v1;
    __syncthreads();
    for (int o = 1; o < 256; o <<= 1) {
        int x = (t >= o) ? sm[t - o] : 0;
        __syncthreads();
        sm[t] += x;
        __syncthreads();
    }
    int ex = (t > 0) ? sm[t - 1] : 0;
    if (i0 < n) g_off[i0] = ex;
    if (i1 < n) g_off[i1] = ex + v0;
    if (t == 255) g_bsum[b] = sm[255];
}

__global__ void scan_spine(int nblk) {
    __shared__ int sm[256];
    int t = threadIdx.x;
    sm[t] = (t < nblk) ? g_bsum[t] : 0;
    __syncthreads();
    for (int o = 1; o < 256; o <<= 1) {
        int x = (t >= o) ? sm[t - o] : 0;
        __syncthreads();
        sm[t] += x;
        __syncthreads();
    }
    g_boff[t] = (t > 0) ? sm[t - 1] : 0;
}

__global__ void scan_add(int n, int e) {
    int i = blockIdx.x * blockDim.x + threadIdx.x;
    if (i < n) g_off[i] += g_boff[i >> 9];
    if (i == 0) g_off[n] = e;
}

// atomic-free fill: position = off[col] + rank
__global__ void fill_kernel(const int* __restrict__ row, const int* __restrict__ col, int e) {
    int i = blockIdx.x * blockDim.x + threadIdx.x;
    int e2 = e >> 1;
    if (i < e2) {
        int2 c = reinterpret_cast<const int2*>(col)[i];
        int2 r = reinterpret_cast<const int2*>(g_rank)[i];
        int2 w = reinterpret_cast<const int2*>(row)[i];
        g_src[g_off[c.x] + r.x] = w.x;
        g_src[g_off[c.y] + r.y] = w.y;
    }
    if (i == 0 && (e & 1))
        g_src[g_off[col[e - 1]] + g_rank[e - 1]] = row[e - 1];
}

// scalar fallbacks (used only when e is odd)
__global__ void hist_rank_scalar(const int* __restrict__ col, int e) {
    int i = blockIdx.x * blockDim.x + threadIdx.x;
    if (i < e) g_rank[i] = atomicAdd(&g_deg[col[i]], 1);
}
__global__ void fill_scalar(const int* __restrict__ row, const int* __restrict__ col, int e) {
    int i = blockIdx.x * blockDim.x + threadIdx.x;
    if (i < e) g_src[g_off[col[i]] + g_rank[i]] = row[i];
}

// dinv + build dinv-scaled half4 layer-1 input
__global__ void dinv_prep_kernel(const float* __restrict__ x, int n) {
    int i = blockIdx.x * blockDim.x + threadIdx.x;
    if (i < n) {
        float dv = rsqrtf((float)(g_deg[i] + 1));  // +1 self loop
        g_dinv[i] = dv;
        __half2 lo = __floats2half2_rn(dv * x[3*i],   dv * x[3*i+1]);
        __half2 hi = __floats2half2_rn(dv * x[3*i+2], 0.0f);
        uint2 w;
        w.x = *reinterpret_cast<unsigned*>(&lo);
        w.y = *reinterpret_cast<unsigned*>(&hi);
        g_s0[i] = w;
    }
}

// ------------------------------- GCN layers -------------------------------

__device__ __forceinline__ void acc_half4(float& a0, float& a1, float& a2, float& a3, uint2 w) {
    float2 f0 = __half22float2(*reinterpret_cast<__half2*>(&w.x));
    float2 f1 = __half22float2(*reinterpret_cast<__half2*>(&w.y));
    a0 += f0.x; a1 += f0.y; a2 += f1.x; a3 += f1.y;
}

// Layer 1 (Cin=3 pad 4 -> Cout=16): edge-per-lane predicated gather.
__global__ void layer1_kernel(const float* __restrict__ W, const float* __restrict__ b,
                              int n) {
    __shared__ float Ws[48];
    __shared__ float bs[16];
    if (threadIdx.x < 48) Ws[threadIdx.x] = W[threadIdx.x];
    if (threadIdx.x < 16) bs[threadIdx.x] = b[threadIdx.x];
    __syncthreads();
    int warp = threadIdx.x >> 5, lane = threadIdx.x & 31;
    int v = blockIdx.x * 8 + warp;
    if (v >= n) return;
    const int jbase = g_off[v];
    const int jend  = g_off[v + 1];
    const int deg   = jend - jbase;
    float ax = 0.0f, ay = 0.0f, az = 0.0f, aw = 0.0f;
    const int nB = (deg + 63) >> 6;
    for (int bb = 0; bb < nB; bb++) {
        int i0 = jbase + lane + bb * 64;
        int i1 = i0 + 32;
        int u0 = (i0 < jend) ? __ldg(&g_src[i0]) : n;
        int u1 = (i1 < jend) ? __ldg(&g_src[i1]) : n;
        acc_half4(ax, ay, az, aw, g_s0[u0]);
        acc_half4(ax, ay, az, aw, g_s0[u1]);
    }
    if (lane == 0) acc_half4(ax, ay, az, aw, g_s0[v]);   // self loop
#pragma unroll
    for (int o = 16; o; o >>= 1) {
        ax += __shfl_xor_sync(0xffffffffu, ax, o);
        ay += __shfl_xor_sync(0xffffffffu, ay, o);
        az += __shfl_xor_sync(0xffffffffu, az, o);
    }
    float dv = g_dinv[v];
    ax *= dv; ay *= dv; az *= dv;
    if (lane < 16) {
        float r = bs[lane] + ax * Ws[lane*3] + ay * Ws[lane*3+1] + az * Ws[lane*3+2];
        __half* outh = reinterpret_cast<__half*>(g_hA);
        outh[v * 16 + lane] = __float2half_rn(dv * fmaxf(r, 0.0f));  // pre-scale
    }
}

// Layers 2-4: edge-group half4 gather, fully predicated (MLP=U everywhere).
// QC = CIN/4 lanes per edge row, EG = edge groups per warp, U = unroll depth.
// IS = input row stride in uint2, OS = output row stride in halfs.
template <int CIN, int COUT, int IS, int OS, int U, bool SCALE>
__global__ void layer_kernel(const uint2* __restrict__ s, __half* __restrict__ outh,
                             const float* __restrict__ W, const float* __restrict__ b,
                             int n) {
    constexpr int QC = CIN / 4;
    constexpr int EG = 32 / QC;
    constexpr int ACT = QC * EG;
    __shared__ float Wt[CIN * COUT];     // transposed: Wt[k*COUT + c]
    __shared__ float bs[COUT];
    __shared__ float aggS[8][CIN];
    for (int i = threadIdx.x; i < CIN * COUT; i += blockDim.x) {
        int c = i / CIN, k = i - c * CIN;
        Wt[k * COUT + c] = W[i];
    }
    if (threadIdx.x < COUT) bs[threadIdx.x] = b[threadIdx.x];
    __syncthreads();
    int warp = threadIdx.x >> 5, lane = threadIdx.x & 31;
    int v = blockIdx.x * 8 + warp;
    if (v >= n) return;
    const float dv = g_dinv[v];
    const int eg = lane / QC;
    const int q  = lane - eg * QC;
    const bool active = (ACT == 32) || (lane < ACT);

    const int jbase = g_off[v];
    const int jend  = g_off[v + 1];
    const int deg   = jend - jbase;

    float a0 = 0.0f, a1 = 0.0f, a2 = 0.0f, a3 = 0.0f;
    if (active && eg == 0)
        acc_half4(a0, a1, a2, a3, s[v * IS + q]);       // self loop
    const int nB = (deg + U * EG - 1) / (U * EG);
    for (int bb = 0; bb < nB; bb++) {
        int base = jbase + eg + (bb * U) * EG;
        int u[U];
#pragma unroll
        for (int k = 0; k < U; k++) {
            int idx = base + k * EG;
            u[k] = (active && idx < jend) ? __ldg(&g_src[idx]) : n;
        }
#pragma unroll
        for (int k = 0; k < U; k++)
            acc_half4(a0, a1, a2, a3, s[u[k] * IS + q]);
    }
    // reduce across edge groups
    if constexpr ((QC & (QC - 1)) == 0) {
#pragma unroll
        for (int o = QC; o < 32; o <<= 1) {
            a0 += __shfl_xor_sync(0xffffffffu, a0, o);
            a1 += __shfl_xor_sync(0xffffffffu, a1, o);
            a2 += __shfl_xor_sync(0xffffffffu, a2, o);
            a3 += __shfl_xor_sync(0xffffffffu, a3, o);
        }
    } else {   // QC=12, EG=2
        a0 += __shfl_down_sync(0xffffffffu, a0, 12);
        a1 += __shfl_down_sync(0xffffffffu, a1, 12);
        a2 += __shfl_down_sync(0xffffffffu, a2, 12);
        a3 += __shfl_down_sync(0xffffffffu, a3, 12);
    }
    if (lane < QC) {
        aggS[warp][q * 4 + 0] = a0 * dv;
        aggS[warp][q * 4 + 1] = a1 * dv;
        aggS[warp][q * 4 + 2] = a2 * dv;
        aggS[warp][q * 4 + 3] = a3 * dv;
    }
    __syncwarp();
    float r0 = bs[lane];
    float r1 = (COUT > 32 && lane + 32 < COUT) ? bs[lane + 32] : 0.0f;
#pragma unroll
    for (int k = 0; k < CIN; k++) {
        float av = aggS[warp][k];                    // broadcast
        r0 += av * Wt[k * COUT + lane];
        if (COUT > 32 && lane + 32 < COUT) r1 += av * Wt[k * COUT + lane + 32];
    }
    r0 = fmaxf(r0, 0.0f);
    if (SCALE) r0 *= dv;
    outh[v * OS + lane] = __float2half_rn(r0);
    if (COUT > 32 && lane + 32 < COUT) {
        r1 = fmaxf(r1, 0.0f);
        if (SCALE) r1 *= dv;
        outh[v * OS + lane + 32] = __float2half_rn(r1);
    }
}

// --------------------------- pool + final MLP ------------------------------

__device__ __forceinline__ void pool_flush(int cur, int c, __half2 m) {
    float2 f = __half22float2(m);
    atomicMax((int*)&g_pool[cur * 64 + 2 * c],     __float_as_int(f.x));
    atomicMax((int*)&g_pool[cur * 64 + 2 * c + 1], __float_as_int(f.y));
}

__global__ void pool_kernel(const __half2* __restrict__ h2, const int* __restrict__ batch, int n) {
    const int NPB = 256;
    int c = threadIdx.x;   // 32 threads = 32 half2 channel pairs
    int start = blockIdx.x * NPB;
    if (start >= n) return;
    int end = start + NPB; if (end > n) end = n;
    int cur = batch[start];
    __half2 m = __float2half2_rn(0.0f);
    for (int v = start; v < end; v++) {
        int gi = batch[v];
        if (gi != cur) {
            pool_flush(cur, c, m);
            cur = gi;
            m = __float2half2_rn(0.0f);
        }
        m = __hmax2(m, h2[v * 32 + c]);
    }
    pool_flush(cur, c, m);
}

__global__ void mlp_kernel(const float* __restrict__ L1w, const float* __restrict__ L1b,
                           const float* __restrict__ L2w, const float* __restrict__ L2b,
                           float* __restrict__ out) {
    __shared__ float gs[64];
    __shared__ float t1[64];
    int gi = blockIdx.x;
    int t = threadIdx.x;   // 64 threads
    gs[t] = g_pool[gi * 64 + t];
    __syncthreads();
    float acc = L1b[t];
#pragma unroll
    for (int k = 0; k < 64; k++) acc += gs[k] * L1w[t * 64 + k];
    t1[t] = fmaxf(acc, 0.0f);
    __syncthreads();
    if (t < 10) {
        float a = L2b[t];
#pragma unroll
        for (int k = 0; k < 64; k++) a += t1[k] * L2w[t * 64 + k];
        out[gi * 10 + t] = a;
    }
}

// ------------------------------- launcher ----------------------------------

extern "C" void kernel_launch(void* const* d_in, const int* in_sizes, int n_in,
                              void* d_out, int out_size) {
    const float* x     = (const float*)d_in[0];
    const int*   ei    = (const int*)d_in[1];
    const int*   batch = (const int*)d_in[2];
    const float* W1 = (const float*)d_in[4];
    const float* b1 = (const float*)d_in[5];
    const float* W2 = (const float*)d_in[6];
    const float* b2 = (const float*)d_in[7];
    const float* W3 = (const float*)d_in[8];
    const float* b3 = (const float*)d_in[9];
    const float* W4 = (const float*)d_in[10];
    const float* b4 = (const float*)d_in[11];
    const float* L1w = (const float*)d_in[12];
    const float* L1b = (const float*)d_in[13];
    const float* L2w = (const float*)d_in[14];
    const float* L2b = (const float*)d_in[15];
    float* out = (float*)d_out;

    const int n = in_sizes[0] / 3;
    const int e = in_sizes[1] / 2;
    const int G = out_size / 10;

    const int* row = ei;
    const int* col = ei + e;

    uint2* hA; cudaGetSymbolAddress((void**)&hA, g_hA);
    uint2* hB; cudaGetSymbolAddress((void**)&hB, g_hB);

    // ---- CSR build + prep ----
    {
        int tot = (n > G * 64) ? n : G * 64;
        init_kernel<<<(tot + 255) / 256, 256>>>(n, G * 64);
        if ((e & 1) == 0)
            hist_rank_kernel<<<((e >> 1) + 255) / 256, 256>>>(col, e);
        else
            hist_rank_scalar<<<(e + 255) / 256, 256>>>(col, e);
        int nblk = (n + 511) / 512;
        scan_local<<<nblk, 256>>>(n);
        scan_spine<<<1, 256>>>(nblk);
        scan_add<<<(n + 255) / 256, 256>>>(n, e);
        if ((e & 1) == 0)
            fill_kernel<<<((e >> 1) + 255) / 256, 256>>>(row, col, e);
        else
            fill_scalar<<<(e + 255) / 256, 256>>>(row, col, e);
        dinv_prep_kernel<<<(n + 255) / 256, 256>>>(x, n);
    }

    const int agg_grid = (n + 7) / 8;   // 8 warps/block, warp per node

    // ---- fused layers: gather(Cin, fp16) -> W -> relu -> (dinv-prescale) ----
    layer1_kernel<<<agg_grid, 256>>>(W1, b1, n);                                    // 3->16 -> hA
    layer_kernel<16, 32, 4,  32, 4, true ><<<agg_grid, 256>>>(hA, (__half*)hB, W2, b2, n); // 16->32 -> hB
    layer_kernel<32, 48, 8,  64, 4, true ><<<agg_grid, 256>>>(hB, (__half*)hA, W3, b3, n); // 32->48 -> hA (128B rows)
    layer_kernel<48, 64, 16, 64, 8, false><<<agg_grid, 256>>>(hA, (__half*)hB, W4, b4, n); // 48->64 -> hB (fp16)

    // ---- pool + MLP ----
    pool_kernel<<<(n + 255) / 256, 32>>>((const __half2*)hB, batch, n);
    mlp_kernel<<<G, 64>>>(L1w, L1b, L2w, L2b, out);
}